// round 6
// baseline (speedup 1.0000x reference)
#include <cuda_runtime.h>
#include <cuda_bf16.h>
#include <cstdint>

#define EDGES      2048
#define DIM        200
#define CH         50
#define KDIM       10000
#define NBLK       4
#define MROWS      8192
#define NNODES     40943
#define GSPLIT     25
#define GKC        400            // KDIM / GSPLIT
#define NSTEP      25             // GKC / 16
#define ECHUNKS    8
#define ECHSZ      256            // EDGES / ECHUNKS
#define CPART_STRIDE (MROWS * DIM)

// ------------------------- static scratch (no allocs) -----------------------
__device__ __align__(16) float g_A[(size_t)NBLK * EDGES * KDIM];      // 327.7 MB
__device__ __align__(16) float g_sck[NBLK * KDIM];
__device__ __align__(16) float g_shk[NBLK * KDIM];
__device__ __align__(16) float g_Cpart[(size_t)GSPLIT * MROWS * DIM]; // 163.8 MB
__device__ __align__(16) float g_Y[MROWS * DIM];
__device__ __align__(16) float g_bn2s[NBLK * DIM];
__device__ __align__(16) float g_bn2h[NBLK * DIM];
__device__ float g_ps[NBLK * CH * ECHUNKS];
__device__ float g_pq[NBLK * CH * ECHUNKS];

// ------------------------------- helpers ------------------------------------
__device__ __forceinline__ void ffma2(unsigned long long& d,
                                      unsigned long long a, unsigned long long b) {
    asm("fma.rn.f32x2 %0, %1, %2, %3;" : "=l"(d) : "l"(a), "l"(b), "l"(d));
}
__device__ __forceinline__ unsigned long long dup2(float x) {
    unsigned long long r; unsigned int u = __float_as_uint(x);
    asm("mov.b64 %0, {%1, %1};" : "=l"(r) : "r"(u));
    return r;
}
__device__ __forceinline__ float bn_relu(float a, float s, float h) {
    return fmaxf(fmaf(a, s, h), 0.0f);
}

// ------------------------------ K0: zero out --------------------------------
__global__ void zero_kernel(float4* __restrict__ out) {
    const size_t total  = (size_t)EDGES * NNODES / 4;
    const size_t stride = (size_t)gridDim.x * blockDim.x;
    for (size_t i = (size_t)blockIdx.x * blockDim.x + threadIdx.x; i < total; i += stride)
        out[i] = make_float4(0.f, 0.f, 0.f, 0.f);
}

// --------------------------- K1: conv1d (raw) -------------------------------
__global__ void conv_kernel(const float* __restrict__ pre_emb, const float* __restrict__ r_emb,
                            const float* __restrict__ W2, const float* __restrict__ b2,
                            const float* __restrict__ W3, const float* __restrict__ b3,
                            const float* __restrict__ W4, const float* __restrict__ b4,
                            const int* __restrict__ src_ids, const int* __restrict__ edge_type,
                            const int* __restrict__ p1, const int* __restrict__ p2,
                            const int* __restrict__ p3) {
    const int e   = blockIdx.x;
    const int b   = blockIdx.y;
    const int tid = threadIdx.x;

    __shared__ float xs[4][204];
    __shared__ float ws[CH * 4 * 3];
    __shared__ float bsm[CH];

    int Cin; const float* W; const float* bias;
    int rel0 = 0, rel1 = 0, rel2 = 0;
    if (b == 0)      { Cin = 2; W = W2; bias = b2; rel0 = p1[e]; }
    else if (b == 1) { Cin = 3; W = W3; bias = b3; rel0 = p2[2*e]; rel1 = p2[2*e+1]; }
    else if (b == 2) { Cin = 4; W = W4; bias = b4; rel0 = p3[3*e]; rel1 = p3[3*e+1]; rel2 = p3[3*e+2]; }
    else             { Cin = 2; W = W2; bias = b2; rel0 = edge_type[e]; }

    const int sid = src_ids[e];
    const float* srcs[4];
    srcs[0] = pre_emb + (size_t)sid  * DIM;
    srcs[1] = r_emb   + (size_t)rel0 * DIM;
    srcs[2] = r_emb   + (size_t)rel1 * DIM;
    srcs[3] = r_emb   + (size_t)rel2 * DIM;

    for (int i = tid; i < Cin * DIM; i += 256) {
        int ch = i / DIM, d = i - ch * DIM;
        xs[ch][d + 1] = srcs[ch][d];
    }
    if (tid < 8) xs[tid >> 1][(tid & 1) ? 201 : 0] = 0.0f;
    for (int i = tid; i < CH * Cin * 3; i += 256) ws[i] = W[i];
    if (tid < CH) bsm[tid] = bias[tid];
    __syncthreads();

    float* outrow = g_A + (size_t)(b * EDGES + e) * KDIM;
    for (int idx = tid; idx < KDIM; idx += 256) {
        int c = idx / DIM, d = idx - c * DIM;
        float y = bsm[c];
        const float* wc = ws + c * Cin * 3;
        for (int i2 = 0; i2 < Cin; i2++)
            y += wc[i2*3+0] * xs[i2][d] + wc[i2*3+1] * xs[i2][d+1] + wc[i2*3+2] * xs[i2][d+2];
        outrow[idx] = y;
    }
}

// ------------------- K2a: BN1 stats stage 1 (per e-chunk) -------------------
__global__ void stats1_kernel() {
    const int chunk = blockIdx.x & (ECHUNKS - 1);
    const int bc    = blockIdx.x >> 3;             // 0..199
    const int b     = bc / CH;
    const int c     = bc - b * CH;
    const int tid   = threadIdx.x;

    __shared__ float ssum[256];
    __shared__ float ssq[256];

    float s[8] = {0,0,0,0,0,0,0,0}, q[8] = {0,0,0,0,0,0,0,0};
    if (tid < DIM) {
        const float* base = g_A + (size_t)b * EDGES * KDIM
                          + (size_t)(chunk * ECHSZ) * KDIM + c * DIM + tid;
        for (int e = 0; e < ECHSZ; e += 8) {
#pragma unroll
            for (int u = 0; u < 8; u++) {
                float v = base[(size_t)(e + u) * KDIM];
                s[u] += v; q[u] += v * v;
            }
        }
    }
    float sa = ((s[0]+s[1])+(s[2]+s[3])) + ((s[4]+s[5])+(s[6]+s[7]));
    float qa = ((q[0]+q[1])+(q[2]+q[3])) + ((q[4]+q[5])+(q[6]+q[7]));
    ssum[tid] = sa; ssq[tid] = qa;
    __syncthreads();
    for (int off = 128; off > 0; off >>= 1) {
        if (tid < off) { ssum[tid] += ssum[tid+off]; ssq[tid] += ssq[tid+off]; }
        __syncthreads();
    }
    if (tid == 0) {
        g_ps[bc * ECHUNKS + chunk] = ssum[0];
        g_pq[bc * ECHUNKS + chunk] = ssq[0];
    }
}

// ------------- K2b: BN1 stats stage 2 -> expanded per-k scale/shift ---------
__global__ void stats2_kernel(const float* __restrict__ g1v, const float* __restrict__ be1v) {
    const int bc  = blockIdx.x;        // 0..199
    const int b   = bc / CH;
    const int c   = bc - b * CH;
    const int tid = threadIdx.x;

    __shared__ float sc_sh[2];
    if (tid == 0) {
        float s = 0.f, q = 0.f;
#pragma unroll
        for (int u = 0; u < ECHUNKS; u++) {
            s += g_ps[bc * ECHUNKS + u];
            q += g_pq[bc * ECHUNKS + u];
        }
        const float inv = 1.0f / (float)(EDGES * DIM);
        float mu  = s * inv;
        float var = q * inv - mu * mu;
        float sc  = g1v[c] * rsqrtf(var + 1e-5f);
        sc_sh[0] = sc;
        sc_sh[1] = be1v[c] - mu * sc;
    }
    __syncthreads();
    if (tid < DIM) {
        g_sck[b * KDIM + c * DIM + tid] = sc_sh[0];
        g_shk[b * KDIM + c * DIM + tid] = sc_sh[1];
    }
}

// ----- K3: fused BN1+ReLU -> f32x2 GEMM, split-K=25, deterministic ----------
// BM=128, BN=208(200 valid), BK=16, 256 thr: TM=4 x TN=26 (32 row-quads x 8 cgs)
__global__ __launch_bounds__(256, 1) void gemm_kernel(const float* __restrict__ Bw) {
    __shared__ __align__(16) float As[2][16][132];
    __shared__ __align__(16) float Bs[2][16][212];

    const int tid = threadIdx.x;
    const int mt  = blockIdx.x;           // 0..63
    const int ks  = blockIdx.y;           // 0..24
    const int m0  = mt * 128;
    const int blk = m0 >> 11;             // decode-block id 0..3
    const int k0  = ks * GKC;

    // A loader: 128x16 floats, two float4 per thread
    const int a_mr = tid >> 1;            // 0..127
    const int a_kq = (tid & 1) * 8;       // 0 or 8
    const float* aptr = g_A   + (size_t)(m0 + a_mr) * KDIM + k0 + a_kq;
    const float* scp  = g_sck + blk * KDIM + k0 + a_kq;
    const float* shp  = g_shk + blk * KDIM + k0 + a_kq;

    // B loader: 200 rows x 16 k = 800 float4 groups; 3-4 per thread
    int gn[4], gk[4];
#pragma unroll
    for (int u = 0; u < 4; u++) { int g = tid + u * 256; gn[u] = g >> 2; gk[u] = (g & 3) * 4; }
    const int gcount = (tid < 32) ? 4 : 3;

    const int r  = tid & 31;              // row quad index (rows 4r..4r+3)
    const int cg = tid >> 5;              // col group 0..7 (26 cols each)

    unsigned long long acc[4][13];
#pragma unroll
    for (int i = 0; i < 4; i++)
#pragma unroll
        for (int j = 0; j < 13; j++) acc[i][j] = 0ull;

    float4 av0, av1, sc0, sc1, sh0, sh1, bv[4];

    // prologue: tile 0
    av0 = *(const float4*)(aptr);     av1 = *(const float4*)(aptr + 4);
    sc0 = *(const float4*)(scp);      sc1 = *(const float4*)(scp + 4);
    sh0 = *(const float4*)(shp);      sh1 = *(const float4*)(shp + 4);
#pragma unroll
    for (int u = 0; u < 4; u++)
        if (u < gcount) bv[u] = *(const float4*)(Bw + (size_t)gn[u] * KDIM + k0 + gk[u]);

    As[0][a_kq+0][a_mr] = bn_relu(av0.x, sc0.x, sh0.x);
    As[0][a_kq+1][a_mr] = bn_relu(av0.y, sc0.y, sh0.y);
    As[0][a_kq+2][a_mr] = bn_relu(av0.z, sc0.z, sh0.z);
    As[0][a_kq+3][a_mr] = bn_relu(av0.w, sc0.w, sh0.w);
    As[0][a_kq+4][a_mr] = bn_relu(av1.x, sc1.x, sh1.x);
    As[0][a_kq+5][a_mr] = bn_relu(av1.y, sc1.y, sh1.y);
    As[0][a_kq+6][a_mr] = bn_relu(av1.z, sc1.z, sh1.z);
    As[0][a_kq+7][a_mr] = bn_relu(av1.w, sc1.w, sh1.w);
#pragma unroll
    for (int u = 0; u < 4; u++)
        if (u < gcount) {
            Bs[0][gk[u]+0][gn[u]] = bv[u].x;
            Bs[0][gk[u]+1][gn[u]] = bv[u].y;
            Bs[0][gk[u]+2][gn[u]] = bv[u].z;
            Bs[0][gk[u]+3][gn[u]] = bv[u].w;
        }

    int p = 0;
    for (int t = 0; t < NSTEP; t++) {
        __syncthreads();
        const bool more = (t + 1 < NSTEP);
        if (more) {
            const int koff = (t + 1) * 16;
            av0 = *(const float4*)(aptr + koff);   av1 = *(const float4*)(aptr + koff + 4);
            sc0 = *(const float4*)(scp + koff);    sc1 = *(const float4*)(scp + koff + 4);
            sh0 = *(const float4*)(shp + koff);    sh1 = *(const float4*)(shp + koff + 4);
#pragma unroll
            for (int u = 0; u < 4; u++)
                if (u < gcount) bv[u] = *(const float4*)(Bw + (size_t)gn[u] * KDIM + k0 + koff + gk[u]);
        }

#pragma unroll
        for (int kk = 0; kk < 16; kk++) {
            float4 a4 = *(const float4*)&As[p][kk][r * 4];
            unsigned long long pa0 = dup2(a4.x);
            unsigned long long pa1 = dup2(a4.y);
            unsigned long long pa2 = dup2(a4.z);
            unsigned long long pa3 = dup2(a4.w);
            const unsigned long long* brow = (const unsigned long long*)&Bs[p][kk][cg * 26];
#pragma unroll
            for (int j = 0; j < 13; j++) {
                unsigned long long bj = brow[j];
                ffma2(acc[0][j], pa0, bj);
                ffma2(acc[1][j], pa1, bj);
                ffma2(acc[2][j], pa2, bj);
                ffma2(acc[3][j], pa3, bj);
            }
        }

        if (more) {
            const int q = p ^ 1;
            As[q][a_kq+0][a_mr] = bn_relu(av0.x, sc0.x, sh0.x);
            As[q][a_kq+1][a_mr] = bn_relu(av0.y, sc0.y, sh0.y);
            As[q][a_kq+2][a_mr] = bn_relu(av0.z, sc0.z, sh0.z);
            As[q][a_kq+3][a_mr] = bn_relu(av0.w, sc0.w, sh0.w);
            As[q][a_kq+4][a_mr] = bn_relu(av1.x, sc1.x, sh1.x);
            As[q][a_kq+5][a_mr] = bn_relu(av1.y, sc1.y, sh1.y);
            As[q][a_kq+6][a_mr] = bn_relu(av1.z, sc1.z, sh1.z);
            As[q][a_kq+7][a_mr] = bn_relu(av1.w, sc1.w, sh1.w);
#pragma unroll
            for (int u = 0; u < 4; u++)
                if (u < gcount) {
                    Bs[q][gk[u]+0][gn[u]] = bv[u].x;
                    Bs[q][gk[u]+1][gn[u]] = bv[u].y;
                    Bs[q][gk[u]+2][gn[u]] = bv[u].z;
                    Bs[q][gk[u]+3][gn[u]] = bv[u].w;
                }
        }
        p ^= 1;
    }

    // epilogue -> split-K partials (packed 8B stores; pairs never straddle 200)
    float* cp = g_Cpart + (size_t)ks * CPART_STRIDE + (size_t)m0 * DIM;
#pragma unroll
    for (int rr = 0; rr < 4; rr++) {
        const int m = r * 4 + rr;
        float* rowp = cp + (size_t)m * DIM;
#pragma unroll
        for (int j = 0; j < 13; j++) {
            const int n = cg * 26 + 2 * j;
            if (n < DIM)
                *(unsigned long long*)(rowp + n) = acc[rr][j];
        }
    }
}

// ----------------- K4: split-K reduce (fixed order) + fc_b ------------------
__global__ void reduce_kernel(const float* __restrict__ fc_b) {
    const int i = blockIdx.x * 256 + threadIdx.x;
    const float4* p = (const float4*)g_Cpart;
    const size_t stride4 = CPART_STRIDE / 4;
    float4 s = p[i];
#pragma unroll
    for (int u = 1; u < GSPLIT; u++) {
        float4 v = p[(size_t)u * stride4 + i];
        s.x += v.x; s.y += v.y; s.z += v.z; s.w += v.w;
    }
    const int n0 = (i * 4) % DIM;
    float4 bb = *(const float4*)(fc_b + n0);
    s.x += bb.x; s.y += bb.y; s.z += bb.z; s.w += bb.w;
    ((float4*)g_Y)[i] = s;
}

// --------------------------- K5: BN2 stats ----------------------------------
__global__ void bn2_kernel(const float* __restrict__ g2v, const float* __restrict__ be2v) {
    const int b   = blockIdx.x / DIM;
    const int n   = blockIdx.x - b * DIM;
    const int tid = threadIdx.x;

    __shared__ float ssum[256];
    __shared__ float ssq[256];

    float s = 0.f, q = 0.f;
    const float* base = g_Y + (size_t)(b * EDGES) * DIM + n;
#pragma unroll
    for (int u = 0; u < 8; u++) {
        float v = base[(size_t)(tid + u * 256) * DIM];
        s += v; q += v * v;
    }
    ssum[tid] = s; ssq[tid] = q;
    __syncthreads();
    for (int off = 128; off > 0; off >>= 1) {
        if (tid < off) { ssum[tid] += ssum[tid+off]; ssq[tid] += ssq[tid+off]; }
        __syncthreads();
    }
    if (tid == 0) {
        const float inv = 1.0f / (float)EDGES;
        float mu  = ssum[0] * inv;
        float var = ssq[0] * inv - mu * mu;
        float sc  = g2v[n] * rsqrtf(var + 1e-5f);
        g_bn2s[b * DIM + n] = sc;
        g_bn2h[b * DIM + n] = be2v[n] - mu * sc;
    }
}

// ----------------- K6: BN2+ReLU, cosine, scatter to output ------------------
__global__ void final_kernel(const int* __restrict__ o, float* __restrict__ out) {
    const int e    = blockIdx.x * 8 + (threadIdx.x >> 5);
    const int lane = threadIdx.x & 31;

    float dot[3] = {0.f,0.f,0.f}, nx[3] = {0.f,0.f,0.f}, nre = 0.f;
    for (int f = lane; f < DIM; f += 32) {
        float re = bn_relu(g_Y[(size_t)(3 * EDGES + e) * DIM + f],
                           g_bn2s[3 * DIM + f], g_bn2h[3 * DIM + f]);
        nre += re * re;
#pragma unroll
        for (int b = 0; b < 3; b++) {
            float xb = bn_relu(g_Y[(size_t)(b * EDGES + e) * DIM + f],
                               g_bn2s[b * DIM + f], g_bn2h[b * DIM + f]);
            dot[b] += xb * re;
            nx[b]  += xb * xb;
        }
    }
#pragma unroll
    for (int off = 16; off > 0; off >>= 1) {
        nre += __shfl_xor_sync(0xffffffffu, nre, off);
#pragma unroll
        for (int b = 0; b < 3; b++) {
            dot[b] += __shfl_xor_sync(0xffffffffu, dot[b], off);
            nx[b]  += __shfl_xor_sync(0xffffffffu, nx[b], off);
        }
    }
    if (lane == 0) {
        float nr = sqrtf(nre);
        float c = 0.f;
#pragma unroll
        for (int b = 0; b < 3; b++)
            c += dot[b] / fmaxf(sqrtf(nx[b]) * nr, 1e-8f);
        out[(size_t)e * NNODES + o[e]] = c;
    }
}

// ---------------------------------------------------------------------------
extern "C" void kernel_launch(void* const* d_in, const int* in_sizes, int n_in,
                              void* d_out, int out_size) {
    const float* pre_emb  = (const float*)d_in[0];
    const float* r_emb    = (const float*)d_in[1];
    const float* W2       = (const float*)d_in[2];
    const float* b2       = (const float*)d_in[3];
    const float* W3       = (const float*)d_in[4];
    const float* b3       = (const float*)d_in[5];
    const float* W4       = (const float*)d_in[6];
    const float* b4       = (const float*)d_in[7];
    const float* fc_w     = (const float*)d_in[8];
    const float* fc_b     = (const float*)d_in[9];
    const float* g1       = (const float*)d_in[10];
    const float* be1      = (const float*)d_in[11];
    const float* g2       = (const float*)d_in[12];
    const float* be2      = (const float*)d_in[13];
    const int*   src_ids  = (const int*)d_in[14];
    const int*   edge_type= (const int*)d_in[15];
    const int*   p1       = (const int*)d_in[16];
    const int*   p2       = (const int*)d_in[17];
    const int*   p3       = (const int*)d_in[18];
    const int*   o        = (const int*)d_in[19];
    float* out = (float*)d_out;

    zero_kernel<<<4096, 256>>>((float4*)out);
    conv_kernel<<<dim3(EDGES, NBLK), 256>>>(pre_emb, r_emb, W2, b2, W3, b3, W4, b4,
                                            src_ids, edge_type, p1, p2, p3);
    stats1_kernel<<<NBLK * CH * ECHUNKS, 256>>>();
    stats2_kernel<<<NBLK * CH, 256>>>(g1, be1);
    gemm_kernel<<<dim3(MROWS / 128, GSPLIT), 256>>>(fc_w);
    reduce_kernel<<<(MROWS * DIM / 4) / 256, 256>>>(fc_b);
    bn2_kernel<<<NBLK * DIM, 256>>>(g2, be2);
    final_kernel<<<EDGES / 8, 256>>>(o, out);
}

// round 8
// speedup vs baseline: 1.2577x; 1.2577x over previous
#include <cuda_runtime.h>
#include <cuda_bf16.h>
#include <cstdint>

#define EDGES      2048
#define DIM        200
#define CH         50
#define KDIM       10000
#define NBLK       4
#define MROWS      8192
#define NNODES     40943
#define ECHUNKS    8
#define ECHSZ      256
#define GSPLIT     2
#define CPART_STRIDE (MROWS * DIM)

// ------------------------- static scratch (no allocs) -----------------------
__device__ __align__(16) float g_A[(size_t)NBLK * EDGES * KDIM];      // 327.7 MB
__device__ __align__(16) float g_sck[NBLK * KDIM];
__device__ __align__(16) float g_shk[NBLK * KDIM];
__device__ __align__(16) float g_Cpart[(size_t)GSPLIT * MROWS * DIM]; // 13.1 MB
__device__ __align__(16) float g_Y[MROWS * DIM];
__device__ __align__(16) float g_bn2s[NBLK * DIM];
__device__ __align__(16) float g_bn2h[NBLK * DIM];
__device__ float g_ps[NBLK * CH * ECHUNKS];
__device__ float g_pq[NBLK * CH * ECHUNKS];

// ------------------------------- helpers ------------------------------------
__device__ __forceinline__ float bn_relu(float a, float s, float h) {
    return fmaxf(fmaf(a, s, h), 0.0f);
}

__device__ __forceinline__ uint32_t smem_u32(const void* p) {
    uint32_t a;
    asm("{ .reg .u64 t; cvta.to.shared.u64 t, %1; cvt.u32.u64 %0, t; }" : "=r"(a) : "l"(p));
    return a;
}

__device__ __forceinline__ void ldsm4(uint32_t* r, uint32_t a) {
    asm volatile("ldmatrix.sync.aligned.m8n8.x4.shared.b16 {%0,%1,%2,%3}, [%4];"
                 : "=r"(r[0]), "=r"(r[1]), "=r"(r[2]), "=r"(r[3]) : "r"(a));
}

__device__ __forceinline__ void mma16816(float* c, const uint32_t* a,
                                         uint32_t b0, uint32_t b1) {
    asm volatile(
        "mma.sync.aligned.m16n8k16.row.col.f32.bf16.bf16.f32 "
        "{%0,%1,%2,%3}, {%4,%5,%6,%7}, {%8,%9}, {%0,%1,%2,%3};"
        : "+f"(c[0]), "+f"(c[1]), "+f"(c[2]), "+f"(c[3])
        : "r"(a[0]), "r"(a[1]), "r"(a[2]), "r"(a[3]), "r"(b0), "r"(b1));
}

__device__ __forceinline__ uint32_t pack_bf2(float a, float b) {
    __nv_bfloat162 t = __floats2bfloat162_rn(a, b);
    return *reinterpret_cast<uint32_t*>(&t);
}

// split 8 fp32 -> hi/lo bf16x8 (uint4 each)
__device__ __forceinline__ void split8(const float* v, uint4& HI, uint4& LO) {
    float hf[8], lf[8];
#pragma unroll
    for (int u = 0; u < 8; u++) {
        __nv_bfloat16 h = __float2bfloat16(v[u]);
        hf[u] = __bfloat162float(h);
        lf[u] = v[u] - hf[u];
    }
    HI.x = pack_bf2(hf[0], hf[1]); HI.y = pack_bf2(hf[2], hf[3]);
    HI.z = pack_bf2(hf[4], hf[5]); HI.w = pack_bf2(hf[6], hf[7]);
    LO.x = pack_bf2(lf[0], lf[1]); LO.y = pack_bf2(lf[2], lf[3]);
    LO.z = pack_bf2(lf[4], lf[5]); LO.w = pack_bf2(lf[6], lf[7]);
}

// SMEM layout (bytes, per double-buffer half). bf16 tiles, row stride 48B.
#define SMA_HI 0
#define SMA_LO 6144
#define SMB_HI 12288
#define SMB_LO 22272
#define SMBUF  32256
#define SMTOT  64512

// ------------------------------ K0: zero out --------------------------------
__global__ void zero_kernel(float4* __restrict__ out) {
    const size_t total  = (size_t)EDGES * NNODES / 4;
    const size_t stride = (size_t)gridDim.x * blockDim.x;
    for (size_t i = (size_t)blockIdx.x * blockDim.x + threadIdx.x; i < total; i += stride)
        out[i] = make_float4(0.f, 0.f, 0.f, 0.f);
}

// --------------------------- K1: conv1d (raw) -------------------------------
__global__ void conv_kernel(const float* __restrict__ pre_emb, const float* __restrict__ r_emb,
                            const float* __restrict__ W2, const float* __restrict__ b2,
                            const float* __restrict__ W3, const float* __restrict__ b3,
                            const float* __restrict__ W4, const float* __restrict__ b4,
                            const int* __restrict__ src_ids, const int* __restrict__ edge_type,
                            const int* __restrict__ p1, const int* __restrict__ p2,
                            const int* __restrict__ p3) {
    const int e   = blockIdx.x;
    const int b   = blockIdx.y;
    const int tid = threadIdx.x;

    __shared__ float xs[4][204];
    __shared__ float ws[CH * 4 * 3];
    __shared__ float bsm[CH];

    int Cin; const float* W; const float* bias;
    int rel0 = 0, rel1 = 0, rel2 = 0;
    if (b == 0)      { Cin = 2; W = W2; bias = b2; rel0 = p1[e]; }
    else if (b == 1) { Cin = 3; W = W3; bias = b3; rel0 = p2[2*e]; rel1 = p2[2*e+1]; }
    else if (b == 2) { Cin = 4; W = W4; bias = b4; rel0 = p3[3*e]; rel1 = p3[3*e+1]; rel2 = p3[3*e+2]; }
    else             { Cin = 2; W = W2; bias = b2; rel0 = edge_type[e]; }

    const int sid = src_ids[e];
    const float* srcs[4];
    srcs[0] = pre_emb + (size_t)sid  * DIM;
    srcs[1] = r_emb   + (size_t)rel0 * DIM;
    srcs[2] = r_emb   + (size_t)rel1 * DIM;
    srcs[3] = r_emb   + (size_t)rel2 * DIM;

    for (int i = tid; i < Cin * DIM; i += 256) {
        int ch = i / DIM, d = i - ch * DIM;
        xs[ch][d + 1] = srcs[ch][d];
    }
    if (tid < 8) xs[tid >> 1][(tid & 1) ? 201 : 0] = 0.0f;
    for (int i = tid; i < CH * Cin * 3; i += 256) ws[i] = W[i];
    if (tid < CH) bsm[tid] = bias[tid];
    __syncthreads();

    float* outrow = g_A + (size_t)(b * EDGES + e) * KDIM;
    for (int idx = tid; idx < KDIM; idx += 256) {
        int c = idx / DIM, d = idx - c * DIM;
        float y = bsm[c];
        const float* wc = ws + c * Cin * 3;
        for (int i2 = 0; i2 < Cin; i2++)
            y += wc[i2*3+0] * xs[i2][d] + wc[i2*3+1] * xs[i2][d+1] + wc[i2*3+2] * xs[i2][d+2];
        outrow[idx] = y;
    }
}

// ------------------- K2a: BN1 stats stage 1 (per e-chunk) -------------------
__global__ void stats1_kernel() {
    const int chunk = blockIdx.x & (ECHUNKS - 1);
    const int bc    = blockIdx.x >> 3;
    const int b     = bc / CH;
    const int c     = bc - b * CH;
    const int tid   = threadIdx.x;

    __shared__ float ssum[256];
    __shared__ float ssq[256];

    float s[8] = {0,0,0,0,0,0,0,0}, q[8] = {0,0,0,0,0,0,0,0};
    if (tid < DIM) {
        const float* base = g_A + (size_t)b * EDGES * KDIM
                          + (size_t)(chunk * ECHSZ) * KDIM + c * DIM + tid;
        for (int e = 0; e < ECHSZ; e += 8) {
#pragma unroll
            for (int u = 0; u < 8; u++) {
                float v = base[(size_t)(e + u) * KDIM];
                s[u] += v; q[u] += v * v;
            }
        }
    }
    float sa = ((s[0]+s[1])+(s[2]+s[3])) + ((s[4]+s[5])+(s[6]+s[7]));
    float qa = ((q[0]+q[1])+(q[2]+q[3])) + ((q[4]+q[5])+(q[6]+q[7]));
    ssum[tid] = sa; ssq[tid] = qa;
    __syncthreads();
    for (int off = 128; off > 0; off >>= 1) {
        if (tid < off) { ssum[tid] += ssum[tid+off]; ssq[tid] += ssq[tid+off]; }
        __syncthreads();
    }
    if (tid == 0) {
        g_ps[bc * ECHUNKS + chunk] = ssum[0];
        g_pq[bc * ECHUNKS + chunk] = ssq[0];
    }
}

// ------------- K2b: BN1 stats stage 2 -> expanded per-k scale/shift ---------
__global__ void stats2_kernel(const float* __restrict__ g1v, const float* __restrict__ be1v) {
    const int bc  = blockIdx.x;
    const int b   = bc / CH;
    const int c   = bc - b * CH;
    const int tid = threadIdx.x;

    __shared__ float sc_sh[2];
    if (tid == 0) {
        float s = 0.f, q = 0.f;
#pragma unroll
        for (int u = 0; u < ECHUNKS; u++) {
            s += g_ps[bc * ECHUNKS + u];
            q += g_pq[bc * ECHUNKS + u];
        }
        const float inv = 1.0f / (float)(EDGES * DIM);
        float mu  = s * inv;
        float var = q * inv - mu * mu;
        float sc  = g1v[c] * rsqrtf(var + 1e-5f);
        sc_sh[0] = sc;
        sc_sh[1] = be1v[c] - mu * sc;
    }
    __syncthreads();
    if (tid < DIM) {
        g_sck[b * KDIM + c * DIM + tid] = sc_sh[0];
        g_shk[b * KDIM + c * DIM + tid] = sc_sh[1];
    }
}

// ---- K3: mma.sync bf16x3 GEMM, fused BN1+ReLU, split-K=2, deterministic ----
// BM=128, BN=200 (25 n8 tiles), BK=16, 256 thr (8 warps x 16 rows).
// acc += Ahi*Bhi + Ahi*Blo + Alo*Bhi   (fp32 accumulate, fixed order)
__global__ __launch_bounds__(256, 1) void gemm_mma_kernel(const float* __restrict__ Bw) {
    extern __shared__ char smem[];
    const uint32_t sbase = smem_u32(smem);
    const int tid  = threadIdx.x;
    const int warp = tid >> 5;
    const int lane = tid & 31;
    const int m0   = blockIdx.x * 128;
    const int ks   = blockIdx.y;
    const int blk  = m0 >> 11;
    const size_t blkK = (size_t)blk * KDIM;

    const int kbeg  = ks ? 312 : 0;     // k16-step start
    const int iters = ks ? 313 : 312;   // 625 total, 10000 = 625*16

    // A loader: row = tid>>1, half = tid&1 covers 8 k-elements
    const int a_row  = tid >> 1;
    const int a_half = tid & 1;
    const float* aptr = g_A   + (size_t)(m0 + a_row) * KDIM + a_half * 8;
    const float* scp  = g_sck + blkK + a_half * 8;
    const float* shp  = g_shk + blkK + a_half * 8;

    // B loader: 400 segments (n, half) of 8 floats
    const int n0 = tid >> 1,         h0 = tid & 1;
    const int n1 = (tid + 256) >> 1, h1 = tid & 1;   // (tid+256)&1 == tid&1
    const bool has2 = (tid < 144);

    float acc[25][4];
#pragma unroll
    for (int i = 0; i < 25; i++)
#pragma unroll
        for (int j = 0; j < 4; j++) acc[i][j] = 0.f;

    float4 ax0, ax1, sc0, sc1, sh0, sh1, b0a, b0b, b1a, b1b;

    // ---- prologue: load k-step kbeg, store to buffer 0 ----
    {
        const int k16 = kbeg * 16;
        ax0 = *(const float4*)(aptr + k16);  ax1 = *(const float4*)(aptr + k16 + 4);
        sc0 = *(const float4*)(scp + k16);   sc1 = *(const float4*)(scp + k16 + 4);
        sh0 = *(const float4*)(shp + k16);   sh1 = *(const float4*)(shp + k16 + 4);
        b0a = *(const float4*)(Bw + (size_t)n0 * KDIM + k16 + h0 * 8);
        b0b = *(const float4*)(Bw + (size_t)n0 * KDIM + k16 + h0 * 8 + 4);
        if (has2) {
            b1a = *(const float4*)(Bw + (size_t)n1 * KDIM + k16 + h1 * 8);
            b1b = *(const float4*)(Bw + (size_t)n1 * KDIM + k16 + h1 * 8 + 4);
        }
        char* base = smem;
        float v[8]; uint4 HI, LO;
        v[0]=bn_relu(ax0.x,sc0.x,sh0.x); v[1]=bn_relu(ax0.y,sc0.y,sh0.y);
        v[2]=bn_relu(ax0.z,sc0.z,sh0.z); v[3]=bn_relu(ax0.w,sc0.w,sh0.w);
        v[4]=bn_relu(ax1.x,sc1.x,sh1.x); v[5]=bn_relu(ax1.y,sc1.y,sh1.y);
        v[6]=bn_relu(ax1.z,sc1.z,sh1.z); v[7]=bn_relu(ax1.w,sc1.w,sh1.w);
        split8(v, HI, LO);
        *(uint4*)(base + SMA_HI + a_row * 48 + a_half * 16) = HI;
        *(uint4*)(base + SMA_LO + a_row * 48 + a_half * 16) = LO;
        v[0]=b0a.x; v[1]=b0a.y; v[2]=b0a.z; v[3]=b0a.w;
        v[4]=b0b.x; v[5]=b0b.y; v[6]=b0b.z; v[7]=b0b.w;
        split8(v, HI, LO);
        *(uint4*)(base + SMB_HI + n0 * 48 + h0 * 16) = HI;
        *(uint4*)(base + SMB_LO + n0 * 48 + h0 * 16) = LO;
        if (has2) {
            v[0]=b1a.x; v[1]=b1a.y; v[2]=b1a.z; v[3]=b1a.w;
            v[4]=b1b.x; v[5]=b1b.y; v[6]=b1b.z; v[7]=b1b.w;
            split8(v, HI, LO);
            *(uint4*)(base + SMB_HI + n1 * 48 + h1 * 16) = HI;
            *(uint4*)(base + SMB_LO + n1 * 48 + h1 * 16) = LO;
        }
    }

    int p = 0;
    for (int t = 0; t < iters; t++) {
        __syncthreads();
        const bool more = (t + 1 < iters);
        if (more) {
            const int k16 = (kbeg + t + 1) * 16;
            ax0 = *(const float4*)(aptr + k16);  ax1 = *(const float4*)(aptr + k16 + 4);
            sc0 = *(const float4*)(scp + k16);   sc1 = *(const float4*)(scp + k16 + 4);
            sh0 = *(const float4*)(shp + k16);   sh1 = *(const float4*)(shp + k16 + 4);
            b0a = *(const float4*)(Bw + (size_t)n0 * KDIM + k16 + h0 * 8);
            b0b = *(const float4*)(Bw + (size_t)n0 * KDIM + k16 + h0 * 8 + 4);
            if (has2) {
                b1a = *(const float4*)(Bw + (size_t)n1 * KDIM + k16 + h1 * 8);
                b1b = *(const float4*)(Bw + (size_t)n1 * KDIM + k16 + h1 * 8 + 4);
            }
        }

        // ---- compute on buffer p ----
        {
            const uint32_t bufb = sbase + (p ? SMBUF : 0);
            uint32_t ah[4], al[4];
            const uint32_t aaddr = bufb + SMA_HI
                                 + (uint32_t)(warp * 16 + (lane & 15)) * 48
                                 + (uint32_t)(lane >> 4) * 16;
            ldsm4(ah, aaddr);
            ldsm4(al, aaddr + (SMA_LO - SMA_HI));

            const uint32_t baddr0 = bufb + SMB_HI
                                  + (uint32_t)(lane & 15) * 48
                                  + (uint32_t)(lane >> 4) * 16;
#pragma unroll
            for (int pr = 0; pr < 13; pr++) {
                uint32_t bh[4], bl[4];
                const uint32_t ba = baddr0 + (uint32_t)(pr * 16 * 48);
                ldsm4(bh, ba);
                ldsm4(bl, ba + (SMB_LO - SMB_HI));
                // n-tile 2*pr  (rows pair*16 + 0..7): frags {R0, R2}
                mma16816(acc[2*pr], ah, bh[0], bh[2]);
                mma16816(acc[2*pr], ah, bl[0], bl[2]);
                mma16816(acc[2*pr], al, bh[0], bh[2]);
                if (pr < 12) {
                    // n-tile 2*pr+1 (rows +8..15): frags {R1, R3}
                    mma16816(acc[2*pr+1], ah, bh[1], bh[3]);
                    mma16816(acc[2*pr+1], ah, bl[1], bl[3]);
                    mma16816(acc[2*pr+1], al, bh[1], bh[3]);
                }
            }
        }

        // ---- store next tile into buffer q ----
        if (more) {
            char* base = smem + (p ? 0 : SMBUF);
            float v[8]; uint4 HI, LO;
            v[0]=bn_relu(ax0.x,sc0.x,sh0.x); v[1]=bn_relu(ax0.y,sc0.y,sh0.y);
            v[2]=bn_relu(ax0.z,sc0.z,sh0.z); v[3]=bn_relu(ax0.w,sc0.w,sh0.w);
            v[4]=bn_relu(ax1.x,sc1.x,sh1.x); v[5]=bn_relu(ax1.y,sc1.y,sh1.y);
            v[6]=bn_relu(ax1.z,sc1.z,sh1.z); v[7]=bn_relu(ax1.w,sc1.w,sh1.w);
            split8(v, HI, LO);
            *(uint4*)(base + SMA_HI + a_row * 48 + a_half * 16) = HI;
            *(uint4*)(base + SMA_LO + a_row * 48 + a_half * 16) = LO;
            v[0]=b0a.x; v[1]=b0a.y; v[2]=b0a.z; v[3]=b0a.w;
            v[4]=b0b.x; v[5]=b0b.y; v[6]=b0b.z; v[7]=b0b.w;
            split8(v, HI, LO);
            *(uint4*)(base + SMB_HI + n0 * 48 + h0 * 16) = HI;
            *(uint4*)(base + SMB_LO + n0 * 48 + h0 * 16) = LO;
            if (has2) {
                v[0]=b1a.x; v[1]=b1a.y; v[2]=b1a.z; v[3]=b1a.w;
                v[4]=b1b.x; v[5]=b1b.y; v[6]=b1b.z; v[7]=b1b.w;
                split8(v, HI, LO);
                *(uint4*)(base + SMB_HI + n1 * 48 + h1 * 16) = HI;
                *(uint4*)(base + SMB_LO + n1 * 48 + h1 * 16) = LO;
            }
        }
        p ^= 1;
    }

    // ---- epilogue: acc -> split-K partial ----
    float* cp = g_Cpart + (size_t)ks * CPART_STRIDE;
    const int rbase = m0 + warp * 16 + (lane >> 2);
    const int cbase = (lane & 3) * 2;
#pragma unroll
    for (int nt = 0; nt < 25; nt++) {
        const int n = nt * 8 + cbase;
        *(float2*)(cp + (size_t)rbase * DIM + n)       = make_float2(acc[nt][0], acc[nt][1]);
        *(float2*)(cp + (size_t)(rbase + 8) * DIM + n) = make_float2(acc[nt][2], acc[nt][3]);
    }
}

// ----------------- K4: split-K reduce (fixed order) + fc_b ------------------
__global__ void reduce_kernel(const float* __restrict__ fc_b) {
    const int i = blockIdx.x * 256 + threadIdx.x;
    const float4* p = (const float4*)g_Cpart;
    const size_t stride4 = CPART_STRIDE / 4;
    float4 s = p[i];
    float4 v = p[stride4 + i];
    s.x += v.x; s.y += v.y; s.z += v.z; s.w += v.w;
    const int n0 = (i * 4) % DIM;
    float4 bb = *(const float4*)(fc_b + n0);
    s.x += bb.x; s.y += bb.y; s.z += bb.z; s.w += bb.w;
    ((float4*)g_Y)[i] = s;
}

// --------------------------- K5: BN2 stats ----------------------------------
__global__ void bn2_kernel(const float* __restrict__ g2v, const float* __restrict__ be2v) {
    const int b   = blockIdx.x / DIM;
    const int n   = blockIdx.x - b * DIM;
    const int tid = threadIdx.x;

    __shared__ float ssum[256];
    __shared__ float ssq[256];

    float s = 0.f, q = 0.f;
    const float* base = g_Y + (size_t)(b * EDGES) * DIM + n;
#pragma unroll
    for (int u = 0; u < 8; u++) {
        float v = base[(size_t)(tid + u * 256) * DIM];
        s += v; q += v * v;
    }
    ssum[tid] = s; ssq[tid] = q;
    __syncthreads();
    for (int off = 128; off > 0; off >>= 1) {
        if (tid < off) { ssum[tid] += ssum[tid+off]; ssq[tid] += ssq[tid+off]; }
        __syncthreads();
    }
    if (tid == 0) {
        const float inv = 1.0f / (float)EDGES;
        float mu  = ssum[0] * inv;
        float var = ssq[0] * inv - mu * mu;
        float sc  = g2v[n] * rsqrtf(var + 1e-5f);
        g_bn2s[b * DIM + n] = sc;
        g_bn2h[b * DIM + n] = be2v[n] - mu * sc;
    }
}

// ----------------- K6: BN2+ReLU, cosine, scatter to output ------------------
__global__ void final_kernel(const int* __restrict__ o, float* __restrict__ out) {
    const int e    = blockIdx.x * 8 + (threadIdx.x >> 5);
    const int lane = threadIdx.x & 31;

    float dot[3] = {0.f,0.f,0.f}, nx[3] = {0.f,0.f,0.f}, nre = 0.f;
    for (int f = lane; f < DIM; f += 32) {
        float re = bn_relu(g_Y[(size_t)(3 * EDGES + e) * DIM + f],
                           g_bn2s[3 * DIM + f], g_bn2h[3 * DIM + f]);
        nre += re * re;
#pragma unroll
        for (int b = 0; b < 3; b++) {
            float xb = bn_relu(g_Y[(size_t)(b * EDGES + e) * DIM + f],
                               g_bn2s[b * DIM + f], g_bn2h[b * DIM + f]);
            dot[b] += xb * re;
            nx[b]  += xb * xb;
        }
    }
#pragma unroll
    for (int off = 16; off > 0; off >>= 1) {
        nre += __shfl_xor_sync(0xffffffffu, nre, off);
#pragma unroll
        for (int b = 0; b < 3; b++) {
            dot[b] += __shfl_xor_sync(0xffffffffu, dot[b], off);
            nx[b]  += __shfl_xor_sync(0xffffffffu, nx[b], off);
        }
    }
    if (lane == 0) {
        float nr = sqrtf(nre);
        float c = 0.f;
#pragma unroll
        for (int b = 0; b < 3; b++)
            c += dot[b] / fmaxf(sqrtf(nx[b]) * nr, 1e-8f);
        out[(size_t)e * NNODES + o[e]] = c;
    }
}

// ---------------------------------------------------------------------------
extern "C" void kernel_launch(void* const* d_in, const int* in_sizes, int n_in,
                              void* d_out, int out_size) {
    const float* pre_emb  = (const float*)d_in[0];
    const float* r_emb    = (const float*)d_in[1];
    const float* W2       = (const float*)d_in[2];
    const float* b2       = (const float*)d_in[3];
    const float* W3       = (const float*)d_in[4];
    const float* b3       = (const float*)d_in[5];
    const float* W4       = (const float*)d_in[6];
    const float* b4       = (const float*)d_in[7];
    const float* fc_w     = (const float*)d_in[8];
    const float* fc_b     = (const float*)d_in[9];
    const float* g1       = (const float*)d_in[10];
    const float* be1      = (const float*)d_in[11];
    const float* g2       = (const float*)d_in[12];
    const float* be2      = (const float*)d_in[13];
    const int*   src_ids  = (const int*)d_in[14];
    const int*   edge_type= (const int*)d_in[15];
    const int*   p1       = (const int*)d_in[16];
    const int*   p2       = (const int*)d_in[17];
    const int*   p3       = (const int*)d_in[18];
    const int*   o        = (const int*)d_in[19];
    float* out = (float*)d_out;

    cudaFuncSetAttribute(gemm_mma_kernel,
                         cudaFuncAttributeMaxDynamicSharedMemorySize, SMTOT);

    zero_kernel<<<4096, 256>>>((float4*)out);
    conv_kernel<<<dim3(EDGES, NBLK), 256>>>(pre_emb, r_emb, W2, b2, W3, b3, W4, b4,
                                            src_ids, edge_type, p1, p2, p3);
    stats1_kernel<<<NBLK * CH * ECHUNKS, 256>>>();
    stats2_kernel<<<NBLK * CH, 256>>>(g1, be1);
    gemm_mma_kernel<<<dim3(MROWS / 128, GSPLIT), 256, SMTOT>>>(fc_w);
    reduce_kernel<<<(MROWS * DIM / 4) / 256, 256>>>(fc_b);
    bn2_kernel<<<NBLK * DIM, 256>>>(g2, be2);
    final_kernel<<<EDGES / 8, 256>>>(o, out);
}

// round 9
// speedup vs baseline: 1.5171x; 1.2063x over previous
#include <cuda_runtime.h>
#include <cuda_bf16.h>
#include <cstdint>

#define EDGES      2048
#define DIM        200
#define CH         50
#define KDIM       10000
#define NBLK       4
#define MROWS      8192
#define NNODES     40943
#define ECHUNKS    8
#define ECHSZ      256
#define GSPLIT     2
#define KG_ROW     1250           // KDIM / 8
#define CPART_STRIDE (MROWS * DIM)

// ------------------------- static scratch (no allocs) -----------------------
__device__ __align__(16) float g_A[(size_t)NBLK * EDGES * KDIM];      // 327.7 MB
__device__ __align__(16) __nv_bfloat16 g_Ahi[(size_t)MROWS * KDIM];   // 163.8 MB
__device__ __align__(16) __nv_bfloat16 g_Alo[(size_t)MROWS * KDIM];   // 163.8 MB
__device__ __align__(16) __nv_bfloat16 g_Bhi[(size_t)DIM * KDIM];     // 4 MB
__device__ __align__(16) __nv_bfloat16 g_Blo[(size_t)DIM * KDIM];     // 4 MB
__device__ __align__(16) float g_sck[NBLK * KDIM];
__device__ __align__(16) float g_shk[NBLK * KDIM];
__device__ __align__(16) float g_Cpart[(size_t)GSPLIT * MROWS * DIM]; // 13.1 MB
__device__ __align__(16) float g_Y[MROWS * DIM];
__device__ __align__(16) float g_bn2s[NBLK * DIM];
__device__ __align__(16) float g_bn2h[NBLK * DIM];
__device__ float g_ps[NBLK * CH * ECHUNKS];
__device__ float g_pq[NBLK * CH * ECHUNKS];

// ------------------------------- helpers ------------------------------------
__device__ __forceinline__ float bn_relu(float a, float s, float h) {
    return fmaxf(fmaf(a, s, h), 0.0f);
}

__device__ __forceinline__ uint32_t smem_u32(const void* p) {
    uint32_t a;
    asm("{ .reg .u64 t; cvta.to.shared.u64 t, %1; cvt.u32.u64 %0, t; }" : "=r"(a) : "l"(p));
    return a;
}

__device__ __forceinline__ void ldsm4(uint32_t* r, uint32_t a) {
    asm volatile("ldmatrix.sync.aligned.m8n8.x4.shared.b16 {%0,%1,%2,%3}, [%4];"
                 : "=r"(r[0]), "=r"(r[1]), "=r"(r[2]), "=r"(r[3]) : "r"(a));
}

__device__ __forceinline__ void mma16816(float* c, const uint32_t* a,
                                         uint32_t b0, uint32_t b1) {
    asm volatile(
        "mma.sync.aligned.m16n8k16.row.col.f32.bf16.bf16.f32 "
        "{%0,%1,%2,%3}, {%4,%5,%6,%7}, {%8,%9}, {%0,%1,%2,%3};"
        : "+f"(c[0]), "+f"(c[1]), "+f"(c[2]), "+f"(c[3])
        : "r"(a[0]), "r"(a[1]), "r"(a[2]), "r"(a[3]), "r"(b0), "r"(b1));
}

__device__ __forceinline__ uint32_t pack_bf2(float a, float b) {
    __nv_bfloat162 t = __floats2bfloat162_rn(a, b);
    return *reinterpret_cast<uint32_t*>(&t);
}

// split 8 fp32 -> hi/lo bf16x8 (uint4 each)
__device__ __forceinline__ void split8(const float* v, uint4& HI, uint4& LO) {
    float hf[8], lf[8];
#pragma unroll
    for (int u = 0; u < 8; u++) {
        __nv_bfloat16 h = __float2bfloat16(v[u]);
        hf[u] = __bfloat162float(h);
        lf[u] = v[u] - hf[u];
    }
    HI.x = pack_bf2(hf[0], hf[1]); HI.y = pack_bf2(hf[2], hf[3]);
    HI.z = pack_bf2(hf[4], hf[5]); HI.w = pack_bf2(hf[6], hf[7]);
    LO.x = pack_bf2(lf[0], lf[1]); LO.y = pack_bf2(lf[2], lf[3]);
    LO.z = pack_bf2(lf[4], lf[5]); LO.w = pack_bf2(lf[6], lf[7]);
}

// SMEM layout (bytes, per double-buffer half). bf16 tiles, row stride 48B.
#define SMA_HI 0
#define SMA_LO 6144
#define SMB_HI 12288
#define SMB_LO 22272
#define SMBUF  32256
#define SMTOT  64512

// ------------------------------ K0: zero out --------------------------------
__global__ void zero_kernel(float4* __restrict__ out) {
    const size_t total  = (size_t)EDGES * NNODES / 4;
    const size_t stride = (size_t)gridDim.x * blockDim.x;
    for (size_t i = (size_t)blockIdx.x * blockDim.x + threadIdx.x; i < total; i += stride)
        out[i] = make_float4(0.f, 0.f, 0.f, 0.f);
}

// --------------------------- K1: conv1d (raw) -------------------------------
__global__ void conv_kernel(const float* __restrict__ pre_emb, const float* __restrict__ r_emb,
                            const float* __restrict__ W2, const float* __restrict__ b2,
                            const float* __restrict__ W3, const float* __restrict__ b3,
                            const float* __restrict__ W4, const float* __restrict__ b4,
                            const int* __restrict__ src_ids, const int* __restrict__ edge_type,
                            const int* __restrict__ p1, const int* __restrict__ p2,
                            const int* __restrict__ p3) {
    const int e   = blockIdx.x;
    const int b   = blockIdx.y;
    const int tid = threadIdx.x;

    __shared__ float xs[4][204];
    __shared__ float ws[CH * 4 * 3];
    __shared__ float bsm[CH];

    int Cin; const float* W; const float* bias;
    int rel0 = 0, rel1 = 0, rel2 = 0;
    if (b == 0)      { Cin = 2; W = W2; bias = b2; rel0 = p1[e]; }
    else if (b == 1) { Cin = 3; W = W3; bias = b3; rel0 = p2[2*e]; rel1 = p2[2*e+1]; }
    else if (b == 2) { Cin = 4; W = W4; bias = b4; rel0 = p3[3*e]; rel1 = p3[3*e+1]; rel2 = p3[3*e+2]; }
    else             { Cin = 2; W = W2; bias = b2; rel0 = edge_type[e]; }

    const int sid = src_ids[e];
    const float* srcs[4];
    srcs[0] = pre_emb + (size_t)sid  * DIM;
    srcs[1] = r_emb   + (size_t)rel0 * DIM;
    srcs[2] = r_emb   + (size_t)rel1 * DIM;
    srcs[3] = r_emb   + (size_t)rel2 * DIM;

    for (int i = tid; i < Cin * DIM; i += 256) {
        int ch = i / DIM, d = i - ch * DIM;
        xs[ch][d + 1] = srcs[ch][d];
    }
    if (tid < 8) xs[tid >> 1][(tid & 1) ? 201 : 0] = 0.0f;
    for (int i = tid; i < CH * Cin * 3; i += 256) ws[i] = W[i];
    if (tid < CH) bsm[tid] = bias[tid];
    __syncthreads();

    float* outrow = g_A + (size_t)(b * EDGES + e) * KDIM;
    for (int idx = tid; idx < KDIM; idx += 256) {
        int c = idx / DIM, d = idx - c * DIM;
        float y = bsm[c];
        const float* wc = ws + c * Cin * 3;
        for (int i2 = 0; i2 < Cin; i2++)
            y += wc[i2*3+0] * xs[i2][d] + wc[i2*3+1] * xs[i2][d+1] + wc[i2*3+2] * xs[i2][d+2];
        outrow[idx] = y;
    }
}

// ------------------- K2a: BN1 stats stage 1 (per e-chunk) -------------------
__global__ void stats1_kernel() {
    const int chunk = blockIdx.x & (ECHUNKS - 1);
    const int bc    = blockIdx.x >> 3;
    const int b     = bc / CH;
    const int c     = bc - b * CH;
    const int tid   = threadIdx.x;

    __shared__ float ssum[256];
    __shared__ float ssq[256];

    float s[8] = {0,0,0,0,0,0,0,0}, q[8] = {0,0,0,0,0,0,0,0};
    if (tid < DIM) {
        const float* base = g_A + (size_t)b * EDGES * KDIM
                          + (size_t)(chunk * ECHSZ) * KDIM + c * DIM + tid;
        for (int e = 0; e < ECHSZ; e += 8) {
#pragma unroll
            for (int u = 0; u < 8; u++) {
                float v = base[(size_t)(e + u) * KDIM];
                s[u] += v; q[u] += v * v;
            }
        }
    }
    float sa = ((s[0]+s[1])+(s[2]+s[3])) + ((s[4]+s[5])+(s[6]+s[7]));
    float qa = ((q[0]+q[1])+(q[2]+q[3])) + ((q[4]+q[5])+(q[6]+q[7]));
    ssum[tid] = sa; ssq[tid] = qa;
    __syncthreads();
    for (int off = 128; off > 0; off >>= 1) {
        if (tid < off) { ssum[tid] += ssum[tid+off]; ssq[tid] += ssq[tid+off]; }
        __syncthreads();
    }
    if (tid == 0) {
        g_ps[bc * ECHUNKS + chunk] = ssum[0];
        g_pq[bc * ECHUNKS + chunk] = ssq[0];
    }
}

// ------------- K2b: BN1 stats stage 2 -> expanded per-k scale/shift ---------
__global__ void stats2_kernel(const float* __restrict__ g1v, const float* __restrict__ be1v) {
    const int bc  = blockIdx.x;
    const int b   = bc / CH;
    const int c   = bc - b * CH;
    const int tid = threadIdx.x;

    __shared__ float sc_sh[2];
    if (tid == 0) {
        float s = 0.f, q = 0.f;
#pragma unroll
        for (int u = 0; u < ECHUNKS; u++) {
            s += g_ps[bc * ECHUNKS + u];
            q += g_pq[bc * ECHUNKS + u];
        }
        const float inv = 1.0f / (float)(EDGES * DIM);
        float mu  = s * inv;
        float var = q * inv - mu * mu;
        float sc  = g1v[c] * rsqrtf(var + 1e-5f);
        sc_sh[0] = sc;
        sc_sh[1] = be1v[c] - mu * sc;
    }
    __syncthreads();
    if (tid < DIM) {
        g_sck[b * KDIM + c * DIM + tid] = sc_sh[0];
        g_shk[b * KDIM + c * DIM + tid] = sc_sh[1];
    }
}

// ------- K2c: BN1+ReLU + bf16 hi/lo split of A (one streaming pass) ---------
__global__ void splitA_kernel() {
    const size_t i = (size_t)blockIdx.x * 256 + threadIdx.x;   // 8-elt group id
    const int m  = (int)(i / KG_ROW);
    const int kg = (int)(i - (size_t)m * KG_ROW);
    const int k  = kg * 8;
    const int blk = m >> 11;
    const size_t off = (size_t)m * KDIM + k;
    const size_t so  = (size_t)blk * KDIM + k;

    float4 x0 = *(const float4*)(g_A + off);
    float4 x1 = *(const float4*)(g_A + off + 4);
    float4 s0 = *(const float4*)(g_sck + so);
    float4 s1 = *(const float4*)(g_sck + so + 4);
    float4 h0 = *(const float4*)(g_shk + so);
    float4 h1 = *(const float4*)(g_shk + so + 4);

    float v[8];
    v[0] = bn_relu(x0.x, s0.x, h0.x); v[1] = bn_relu(x0.y, s0.y, h0.y);
    v[2] = bn_relu(x0.z, s0.z, h0.z); v[3] = bn_relu(x0.w, s0.w, h0.w);
    v[4] = bn_relu(x1.x, s1.x, h1.x); v[5] = bn_relu(x1.y, s1.y, h1.y);
    v[6] = bn_relu(x1.z, s1.z, h1.z); v[7] = bn_relu(x1.w, s1.w, h1.w);

    uint4 HI, LO;
    split8(v, HI, LO);
    ((uint4*)g_Ahi)[i] = HI;
    ((uint4*)g_Alo)[i] = LO;
}

// ---------------- K2d: bf16 hi/lo split of fc_w (once) ----------------------
__global__ void splitB_kernel(const float* __restrict__ Bw) {
    const size_t i = (size_t)blockIdx.x * 256 + threadIdx.x;
    if (i >= (size_t)DIM * KG_ROW) return;
    const size_t off = i * 8;
    float4 x0 = *(const float4*)(Bw + off);
    float4 x1 = *(const float4*)(Bw + off + 4);
    float v[8] = {x0.x, x0.y, x0.z, x0.w, x1.x, x1.y, x1.z, x1.w};
    uint4 HI, LO;
    split8(v, HI, LO);
    ((uint4*)g_Bhi)[i] = HI;
    ((uint4*)g_Blo)[i] = LO;
}

// ---- K3: mma.sync bf16x3 GEMM on preconverted tiles, split-K=2 -------------
// BM=128, BN=200 (25 n8 tiles), BK=16, 256 thr (8 warps x 16 rows).
// acc += Ahi*Bhi + Ahi*Blo + Alo*Bhi   (fp32 accumulate, fixed order)
__global__ __launch_bounds__(256, 1) void gemm_mma_kernel() {
    extern __shared__ char smem[];
    const uint32_t sbase = smem_u32(smem);
    const int tid  = threadIdx.x;
    const int warp = tid >> 5;
    const int lane = tid & 31;
    const int m0   = blockIdx.x * 128;
    const int ks   = blockIdx.y;

    const int kbeg  = ks ? 312 : 0;     // k16-step start
    const int iters = ks ? 313 : 312;   // 625 total, 10000 = 625*16

    // A loader: row = tid>>1, half = tid&1 covers 8 k-elements (16B bf16)
    const int a_row  = tid >> 1;
    const int a_half = tid & 1;
    const __nv_bfloat16* ahp = g_Ahi + (size_t)(m0 + a_row) * KDIM + a_half * 8;
    const __nv_bfloat16* alp = g_Alo + (size_t)(m0 + a_row) * KDIM + a_half * 8;

    // B loader: 400 segments (n, half) of 8 bf16
    const int n0 = tid >> 1,         h0 = tid & 1;
    const int n1 = (tid + 256) >> 1, h1 = tid & 1;
    const bool has2 = (tid < 144);
    const __nv_bfloat16* b0hp = g_Bhi + (size_t)n0 * KDIM + h0 * 8;
    const __nv_bfloat16* b0lp = g_Blo + (size_t)n0 * KDIM + h0 * 8;
    const __nv_bfloat16* b1hp = g_Bhi + (size_t)n1 * KDIM + h1 * 8;
    const __nv_bfloat16* b1lp = g_Blo + (size_t)n1 * KDIM + h1 * 8;

    float acc[25][4];
#pragma unroll
    for (int i = 0; i < 25; i++)
#pragma unroll
        for (int j = 0; j < 4; j++) acc[i][j] = 0.f;

    uint4 rAH, rAL, rB0H, rB0L, rB1H, rB1L;

    // ---- prologue: load k-step kbeg, store to buffer 0 ----
    {
        const int k16 = kbeg * 16;
        rAH  = *(const uint4*)(ahp + k16);
        rAL  = *(const uint4*)(alp + k16);
        rB0H = *(const uint4*)(b0hp + k16);
        rB0L = *(const uint4*)(b0lp + k16);
        if (has2) {
            rB1H = *(const uint4*)(b1hp + k16);
            rB1L = *(const uint4*)(b1lp + k16);
        }
        char* base = smem;
        *(uint4*)(base + SMA_HI + a_row * 48 + a_half * 16) = rAH;
        *(uint4*)(base + SMA_LO + a_row * 48 + a_half * 16) = rAL;
        *(uint4*)(base + SMB_HI + n0 * 48 + h0 * 16) = rB0H;
        *(uint4*)(base + SMB_LO + n0 * 48 + h0 * 16) = rB0L;
        if (has2) {
            *(uint4*)(base + SMB_HI + n1 * 48 + h1 * 16) = rB1H;
            *(uint4*)(base + SMB_LO + n1 * 48 + h1 * 16) = rB1L;
        }
    }

    int p = 0;
    for (int t = 0; t < iters; t++) {
        __syncthreads();
        const bool more = (t + 1 < iters);
        if (more) {
            const int k16 = (kbeg + t + 1) * 16;
            rAH  = *(const uint4*)(ahp + k16);
            rAL  = *(const uint4*)(alp + k16);
            rB0H = *(const uint4*)(b0hp + k16);
            rB0L = *(const uint4*)(b0lp + k16);
            if (has2) {
                rB1H = *(const uint4*)(b1hp + k16);
                rB1L = *(const uint4*)(b1lp + k16);
            }
        }

        // ---- compute on buffer p ----
        {
            const uint32_t bufb = sbase + (p ? SMBUF : 0);
            uint32_t ah[4], al[4];
            const uint32_t aaddr = bufb + SMA_HI
                                 + (uint32_t)(warp * 16 + (lane & 15)) * 48
                                 + (uint32_t)(lane >> 4) * 16;
            ldsm4(ah, aaddr);
            ldsm4(al, aaddr + (SMA_LO - SMA_HI));

            const uint32_t baddr0 = bufb + SMB_HI
                                  + (uint32_t)(lane & 15) * 48
                                  + (uint32_t)(lane >> 4) * 16;
#pragma unroll
            for (int pr = 0; pr < 13; pr++) {
                uint32_t bh[4], bl[4];
                const uint32_t ba = baddr0 + (uint32_t)(pr * 16 * 48);
                ldsm4(bh, ba);
                ldsm4(bl, ba + (SMB_LO - SMB_HI));
                mma16816(acc[2*pr], ah, bh[0], bh[2]);
                mma16816(acc[2*pr], ah, bl[0], bl[2]);
                mma16816(acc[2*pr], al, bh[0], bh[2]);
                if (pr < 12) {
                    mma16816(acc[2*pr+1], ah, bh[1], bh[3]);
                    mma16816(acc[2*pr+1], ah, bl[1], bl[3]);
                    mma16816(acc[2*pr+1], al, bh[1], bh[3]);
                }
            }
        }

        // ---- store next tile into buffer q ----
        if (more) {
            char* base = smem + (p ? 0 : SMBUF);
            *(uint4*)(base + SMA_HI + a_row * 48 + a_half * 16) = rAH;
            *(uint4*)(base + SMA_LO + a_row * 48 + a_half * 16) = rAL;
            *(uint4*)(base + SMB_HI + n0 * 48 + h0 * 16) = rB0H;
            *(uint4*)(base + SMB_LO + n0 * 48 + h0 * 16) = rB0L;
            if (has2) {
                *(uint4*)(base + SMB_HI + n1 * 48 + h1 * 16) = rB1H;
                *(uint4*)(base + SMB_LO + n1 * 48 + h1 * 16) = rB1L;
            }
        }
        p ^= 1;
    }

    // ---- epilogue: acc -> split-K partial ----
    float* cp = g_Cpart + (size_t)ks * CPART_STRIDE;
    const int rbase = m0 + warp * 16 + (lane >> 2);
    const int cbase = (lane & 3) * 2;
#pragma unroll
    for (int nt = 0; nt < 25; nt++) {
        const int n = nt * 8 + cbase;
        *(float2*)(cp + (size_t)rbase * DIM + n)       = make_float2(acc[nt][0], acc[nt][1]);
        *(float2*)(cp + (size_t)(rbase + 8) * DIM + n) = make_float2(acc[nt][2], acc[nt][3]);
    }
}

// ----------------- K4: split-K reduce (fixed order) + fc_b ------------------
__global__ void reduce_kernel(const float* __restrict__ fc_b) {
    const int i = blockIdx.x * 256 + threadIdx.x;
    const float4* p = (const float4*)g_Cpart;
    const size_t stride4 = CPART_STRIDE / 4;
    float4 s = p[i];
    float4 v = p[stride4 + i];
    s.x += v.x; s.y += v.y; s.z += v.z; s.w += v.w;
    const int n0 = (i * 4) % DIM;
    float4 bb = *(const float4*)(fc_b + n0);
    s.x += bb.x; s.y += bb.y; s.z += bb.z; s.w += bb.w;
    ((float4*)g_Y)[i] = s;
}

// --------------------------- K5: BN2 stats ----------------------------------
__global__ void bn2_kernel(const float* __restrict__ g2v, const float* __restrict__ be2v) {
    const int b   = blockIdx.x / DIM;
    const int n   = blockIdx.x - b * DIM;
    const int tid = threadIdx.x;

    __shared__ float ssum[256];
    __shared__ float ssq[256];

    float s = 0.f, q = 0.f;
    const float* base = g_Y + (size_t)(b * EDGES) * DIM + n;
#pragma unroll
    for (int u = 0; u < 8; u++) {
        float v = base[(size_t)(tid + u * 256) * DIM];
        s += v; q += v * v;
    }
    ssum[tid] = s; ssq[tid] = q;
    __syncthreads();
    for (int off = 128; off > 0; off >>= 1) {
        if (tid < off) { ssum[tid] += ssum[tid+off]; ssq[tid] += ssq[tid+off]; }
        __syncthreads();
    }
    if (tid == 0) {
        const float inv = 1.0f / (float)EDGES;
        float mu  = ssum[0] * inv;
        float var = ssq[0] * inv - mu * mu;
        float sc  = g2v[n] * rsqrtf(var + 1e-5f);
        g_bn2s[b * DIM + n] = sc;
        g_bn2h[b * DIM + n] = be2v[n] - mu * sc;
    }
}

// ----------------- K6: BN2+ReLU, cosine, scatter to output ------------------
__global__ void final_kernel(const int* __restrict__ o, float* __restrict__ out) {
    const int e    = blockIdx.x * 8 + (threadIdx.x >> 5);
    const int lane = threadIdx.x & 31;

    float dot[3] = {0.f,0.f,0.f}, nx[3] = {0.f,0.f,0.f}, nre = 0.f;
    for (int f = lane; f < DIM; f += 32) {
        float re = bn_relu(g_Y[(size_t)(3 * EDGES + e) * DIM + f],
                           g_bn2s[3 * DIM + f], g_bn2h[3 * DIM + f]);
        nre += re * re;
#pragma unroll
        for (int b = 0; b < 3; b++) {
            float xb = bn_relu(g_Y[(size_t)(b * EDGES + e) * DIM + f],
                               g_bn2s[b * DIM + f], g_bn2h[b * DIM + f]);
            dot[b] += xb * re;
            nx[b]  += xb * xb;
        }
    }
#pragma unroll
    for (int off = 16; off > 0; off >>= 1) {
        nre += __shfl_xor_sync(0xffffffffu, nre, off);
#pragma unroll
        for (int b = 0; b < 3; b++) {
            dot[b] += __shfl_xor_sync(0xffffffffu, dot[b], off);
            nx[b]  += __shfl_xor_sync(0xffffffffu, nx[b], off);
        }
    }
    if (lane == 0) {
        float nr = sqrtf(nre);
        float c = 0.f;
#pragma unroll
        for (int b = 0; b < 3; b++)
            c += dot[b] / fmaxf(sqrtf(nx[b]) * nr, 1e-8f);
        out[(size_t)e * NNODES + o[e]] = c;
    }
}

// ---------------------------------------------------------------------------
extern "C" void kernel_launch(void* const* d_in, const int* in_sizes, int n_in,
                              void* d_out, int out_size) {
    const float* pre_emb  = (const float*)d_in[0];
    const float* r_emb    = (const float*)d_in[1];
    const float* W2       = (const float*)d_in[2];
    const float* b2       = (const float*)d_in[3];
    const float* W3       = (const float*)d_in[4];
    const float* b3       = (const float*)d_in[5];
    const float* W4       = (const float*)d_in[6];
    const float* b4       = (const float*)d_in[7];
    const float* fc_w     = (const float*)d_in[8];
    const float* fc_b     = (const float*)d_in[9];
    const float* g1       = (const float*)d_in[10];
    const float* be1      = (const float*)d_in[11];
    const float* g2       = (const float*)d_in[12];
    const float* be2      = (const float*)d_in[13];
    const int*   src_ids  = (const int*)d_in[14];
    const int*   edge_type= (const int*)d_in[15];
    const int*   p1       = (const int*)d_in[16];
    const int*   p2       = (const int*)d_in[17];
    const int*   p3       = (const int*)d_in[18];
    const int*   o        = (const int*)d_in[19];
    float* out = (float*)d_out;

    cudaFuncSetAttribute(gemm_mma_kernel,
                         cudaFuncAttributeMaxDynamicSharedMemorySize, SMTOT);

    zero_kernel<<<4096, 256>>>((float4*)out);
    conv_kernel<<<dim3(EDGES, NBLK), 256>>>(pre_emb, r_emb, W2, b2, W3, b3, W4, b4,
                                            src_ids, edge_type, p1, p2, p3);
    stats1_kernel<<<NBLK * CH * ECHUNKS, 256>>>();
    stats2_kernel<<<NBLK * CH, 256>>>(g1, be1);
    splitA_kernel<<<(MROWS * KG_ROW) / 256, 256>>>();
    splitB_kernel<<<(DIM * KG_ROW + 255) / 256, 256>>>(fc_w);
    gemm_mma_kernel<<<dim3(MROWS / 128, GSPLIT), 256, SMTOT>>>();
    reduce_kernel<<<(MROWS * DIM / 4) / 256, 256>>>(fc_b);
    bn2_kernel<<<NBLK * DIM, 256>>>(g2, be2);
    final_kernel<<<EDGES / 8, 256>>>(o, out);
}

// round 10
// speedup vs baseline: 1.7558x; 1.1573x over previous
#include <cuda_runtime.h>
#include <cuda_bf16.h>
#include <cstdint>

#define EDGES      2048
#define DIM        200
#define CH         50
#define KDIM       10000
#define NBLK       4
#define MROWS      8192
#define NNODES     40943
#define GSPLIT     2
#define KG_ROW     1250           // KDIM / 8
#define A_GROUPS   40000          // MROWS * KG_ROW / 256
#define B_GROUPS   977            // ceil(DIM * KG_ROW / 256)
#define CPART_STRIDE (MROWS * DIM)

// ------------------------- static scratch (no allocs) -----------------------
__device__ __align__(16) float g_A[(size_t)NBLK * EDGES * KDIM];      // 327.7 MB
__device__ __align__(16) __nv_bfloat16 g_Ahi[(size_t)MROWS * KDIM];   // 163.8 MB
__device__ __align__(16) __nv_bfloat16 g_Bhi[(size_t)DIM * KDIM];     // 4 MB
__device__ __align__(16) __nv_bfloat16 g_Blo[(size_t)DIM * KDIM];     // 4 MB
__device__ __align__(16) float g_sck[NBLK * KDIM];
__device__ __align__(16) float g_shk[NBLK * KDIM];
__device__ __align__(16) float g_Cpart[(size_t)GSPLIT * MROWS * DIM]; // 13.1 MB
__device__ __align__(16) float g_Y[MROWS * DIM];
__device__ __align__(16) float g_bn2s[NBLK * DIM];
__device__ __align__(16) float g_bn2h[NBLK * DIM];
__device__ float g_eps[NBLK * CH * EDGES];    // per-edge BN1 partial sums
__device__ float g_eq[NBLK * CH * EDGES];     // per-edge BN1 partial sumsq

// ------------------------------- helpers ------------------------------------
__device__ __forceinline__ float bn_relu(float a, float s, float h) {
    return fmaxf(fmaf(a, s, h), 0.0f);
}

__device__ __forceinline__ uint32_t smem_u32(const void* p) {
    uint32_t a;
    asm("{ .reg .u64 t; cvta.to.shared.u64 t, %1; cvt.u32.u64 %0, t; }" : "=r"(a) : "l"(p));
    return a;
}

__device__ __forceinline__ void ldsm4(uint32_t* r, uint32_t a) {
    asm volatile("ldmatrix.sync.aligned.m8n8.x4.shared.b16 {%0,%1,%2,%3}, [%4];"
                 : "=r"(r[0]), "=r"(r[1]), "=r"(r[2]), "=r"(r[3]) : "r"(a));
}

__device__ __forceinline__ void mma16816(float* c, const uint32_t* a,
                                         uint32_t b0, uint32_t b1) {
    asm volatile(
        "mma.sync.aligned.m16n8k16.row.col.f32.bf16.bf16.f32 "
        "{%0,%1,%2,%3}, {%4,%5,%6,%7}, {%8,%9}, {%0,%1,%2,%3};"
        : "+f"(c[0]), "+f"(c[1]), "+f"(c[2]), "+f"(c[3])
        : "r"(a[0]), "r"(a[1]), "r"(a[2]), "r"(a[3]), "r"(b0), "r"(b1));
}

__device__ __forceinline__ uint32_t pack_bf2(float a, float b) {
    __nv_bfloat162 t = __floats2bfloat162_rn(a, b);
    return *reinterpret_cast<uint32_t*>(&t);
}

// round 8 fp32 -> bf16x8 (uint4)
__device__ __forceinline__ uint4 round8(const float* v) {
    uint4 HI;
    HI.x = pack_bf2(v[0], v[1]); HI.y = pack_bf2(v[2], v[3]);
    HI.z = pack_bf2(v[4], v[5]); HI.w = pack_bf2(v[6], v[7]);
    return HI;
}

// split 8 fp32 -> hi/lo bf16x8 (uint4 each)
__device__ __forceinline__ void split8(const float* v, uint4& HI, uint4& LO) {
    float hf[8], lf[8];
#pragma unroll
    for (int u = 0; u < 8; u++) {
        __nv_bfloat16 h = __float2bfloat16(v[u]);
        hf[u] = __bfloat162float(h);
        lf[u] = v[u] - hf[u];
    }
    HI.x = pack_bf2(hf[0], hf[1]); HI.y = pack_bf2(hf[2], hf[3]);
    HI.z = pack_bf2(hf[4], hf[5]); HI.w = pack_bf2(hf[6], hf[7]);
    LO.x = pack_bf2(lf[0], lf[1]); LO.y = pack_bf2(lf[2], lf[3]);
    LO.z = pack_bf2(lf[4], lf[5]); LO.w = pack_bf2(lf[6], lf[7]);
}

// SMEM layout (bytes, per double-buffer half). bf16 tiles, row stride 48B.
#define SMA    0
#define SMB_HI 6144
#define SMB_LO 16128
#define SMBUF  26112
#define SMTOT  52224

// --------- K1: conv1d + fused per-edge BN1 partial sums (deterministic) -----
__global__ void conv_kernel(const float* __restrict__ pre_emb, const float* __restrict__ r_emb,
                            const float* __restrict__ W2, const float* __restrict__ b2,
                            const float* __restrict__ W3, const float* __restrict__ b3,
                            const float* __restrict__ W4, const float* __restrict__ b4,
                            const int* __restrict__ src_ids, const int* __restrict__ edge_type,
                            const int* __restrict__ p1, const int* __restrict__ p2,
                            const int* __restrict__ p3) {
    const int e   = blockIdx.x;
    const int b   = blockIdx.y;
    const int tid = threadIdx.x;

    __shared__ float ys[KDIM];        // 40000 B staged tile
    __shared__ float xs[4][204];
    __shared__ float ws[CH * 4 * 3];
    __shared__ float bsm[CH];

    int Cin; const float* W; const float* bias;
    int rel0 = 0, rel1 = 0, rel2 = 0;
    if (b == 0)      { Cin = 2; W = W2; bias = b2; rel0 = p1[e]; }
    else if (b == 1) { Cin = 3; W = W3; bias = b3; rel0 = p2[2*e]; rel1 = p2[2*e+1]; }
    else if (b == 2) { Cin = 4; W = W4; bias = b4; rel0 = p3[3*e]; rel1 = p3[3*e+1]; rel2 = p3[3*e+2]; }
    else             { Cin = 2; W = W2; bias = b2; rel0 = edge_type[e]; }

    const int sid = src_ids[e];
    const float* srcs[4];
    srcs[0] = pre_emb + (size_t)sid  * DIM;
    srcs[1] = r_emb   + (size_t)rel0 * DIM;
    srcs[2] = r_emb   + (size_t)rel1 * DIM;
    srcs[3] = r_emb   + (size_t)rel2 * DIM;

    for (int i = tid; i < Cin * DIM; i += 256) {
        int ch = i / DIM, d = i - ch * DIM;
        xs[ch][d + 1] = srcs[ch][d];
    }
    if (tid < 8) xs[tid >> 1][(tid & 1) ? 201 : 0] = 0.0f;
    for (int i = tid; i < CH * Cin * 3; i += 256) ws[i] = W[i];
    if (tid < CH) bsm[tid] = bias[tid];
    __syncthreads();

    float* outrow = g_A + (size_t)(b * EDGES + e) * KDIM;
    for (int idx = tid; idx < KDIM; idx += 256) {
        int c = idx / DIM, d = idx - c * DIM;
        float y = bsm[c];
        const float* wc = ws + c * Cin * 3;
        for (int i2 = 0; i2 < Cin; i2++)
            y += wc[i2*3+0] * xs[i2][d] + wc[i2*3+1] * xs[i2][d+1] + wc[i2*3+2] * xs[i2][d+2];
        ys[idx] = y;
        outrow[idx] = y;
    }
    __syncthreads();

    // per-channel partial sums over this edge's 200 values (warp-owned channels)
    const int w    = tid >> 5;
    const int lane = tid & 31;
    for (int c = w; c < CH; c += 8) {
        float s = 0.f, q = 0.f;
        for (int d = lane; d < DIM; d += 32) {
            float v = ys[c * DIM + d];
            s += v; q += v * v;
        }
#pragma unroll
        for (int off = 16; off > 0; off >>= 1) {
            s += __shfl_xor_sync(0xffffffffu, s, off);
            q += __shfl_xor_sync(0xffffffffu, q, off);
        }
        if (lane == 0) {
            g_eps[(b * CH + c) * EDGES + e] = s;
            g_eq [(b * CH + c) * EDGES + e] = q;
        }
    }
}

// ------ K2: reduce per-edge partials -> expanded per-k scale/shift ----------
__global__ void statsr_kernel(const float* __restrict__ g1v, const float* __restrict__ be1v) {
    const int bc  = blockIdx.x;        // 0..199
    const int b   = bc / CH;
    const int c   = bc - b * CH;
    const int tid = threadIdx.x;

    __shared__ float ssum[256];
    __shared__ float ssq[256];

    float s = 0.f, q = 0.f;
#pragma unroll
    for (int u = 0; u < 8; u++) {
        const int e = tid + u * 256;
        s += g_eps[bc * EDGES + e];
        q += g_eq [bc * EDGES + e];
    }
    ssum[tid] = s; ssq[tid] = q;
    __syncthreads();
    for (int off = 128; off > 0; off >>= 1) {
        if (tid < off) { ssum[tid] += ssum[tid+off]; ssq[tid] += ssq[tid+off]; }
        __syncthreads();
    }
    __shared__ float sc_sh[2];
    if (tid == 0) {
        const float inv = 1.0f / (float)(EDGES * DIM);
        float mu  = ssum[0] * inv;
        float var = ssq[0] * inv - mu * mu;
        float sc  = g1v[c] * rsqrtf(var + 1e-5f);
        sc_sh[0] = sc;
        sc_sh[1] = be1v[c] - mu * sc;
    }
    __syncthreads();
    if (tid < DIM) {
        g_sck[b * KDIM + c * DIM + tid] = sc_sh[0];
        g_shk[b * KDIM + c * DIM + tid] = sc_sh[1];
    }
}

// ---- K3: BN1+ReLU+round A -> bf16 (hi only); split fc_w -> hi/lo bf16 ------
__global__ void splitAB_kernel(const float* __restrict__ Bw) {
    const int gid = blockIdx.x;
    if (gid < A_GROUPS) {
        const size_t i = (size_t)gid * 256 + threadIdx.x;   // 8-elt group id
        const int m  = (int)(i / KG_ROW);
        const int kg = (int)(i - (size_t)m * KG_ROW);
        const int k  = kg * 8;
        const int blk = m >> 11;
        const size_t off = (size_t)m * KDIM + k;
        const size_t so  = (size_t)blk * KDIM + k;

        float4 x0 = *(const float4*)(g_A + off);
        float4 x1 = *(const float4*)(g_A + off + 4);
        float4 s0 = *(const float4*)(g_sck + so);
        float4 s1 = *(const float4*)(g_sck + so + 4);
        float4 h0 = *(const float4*)(g_shk + so);
        float4 h1 = *(const float4*)(g_shk + so + 4);

        float v[8];
        v[0] = bn_relu(x0.x, s0.x, h0.x); v[1] = bn_relu(x0.y, s0.y, h0.y);
        v[2] = bn_relu(x0.z, s0.z, h0.z); v[3] = bn_relu(x0.w, s0.w, h0.w);
        v[4] = bn_relu(x1.x, s1.x, h1.x); v[5] = bn_relu(x1.y, s1.y, h1.y);
        v[6] = bn_relu(x1.z, s1.z, h1.z); v[7] = bn_relu(x1.w, s1.w, h1.w);

        ((uint4*)g_Ahi)[i] = round8(v);
    } else {
        const size_t i = (size_t)(gid - A_GROUPS) * 256 + threadIdx.x;
        if (i < (size_t)DIM * KG_ROW) {
            const size_t off = i * 8;
            float4 x0 = *(const float4*)(Bw + off);
            float4 x1 = *(const float4*)(Bw + off + 4);
            float v[8] = {x0.x, x0.y, x0.z, x0.w, x1.x, x1.y, x1.z, x1.w};
            uint4 HI, LO;
            split8(v, HI, LO);
            ((uint4*)g_Bhi)[i] = HI;
            ((uint4*)g_Blo)[i] = LO;
        }
    }
}

// ---- K4: mma.sync 2-product GEMM: Ahi*(Bhi+Blo), split-K=2 -----------------
// BM=128, BN=200 (25 n8 tiles), BK=16, 256 thr (8 warps x 16 rows).
__global__ __launch_bounds__(256, 1) void gemm_mma_kernel() {
    extern __shared__ char smem[];
    const uint32_t sbase = smem_u32(smem);
    const int tid  = threadIdx.x;
    const int warp = tid >> 5;
    const int lane = tid & 31;
    const int m0   = blockIdx.x * 128;
    const int ks   = blockIdx.y;

    const int kbeg  = ks ? 312 : 0;     // k16-step start
    const int iters = ks ? 313 : 312;   // 625 total, 10000 = 625*16

    // A loader: row = tid>>1, half = tid&1 covers 8 k-elements (16B bf16)
    const int a_row  = tid >> 1;
    const int a_half = tid & 1;
    const __nv_bfloat16* ahp = g_Ahi + (size_t)(m0 + a_row) * KDIM + a_half * 8;

    // B loader: 400 segments (n, half) of 8 bf16, hi+lo each
    const int n0 = tid >> 1,         h0 = tid & 1;
    const int n1 = (tid + 256) >> 1, h1 = tid & 1;
    const bool has2 = (tid < 144);
    const __nv_bfloat16* b0hp = g_Bhi + (size_t)n0 * KDIM + h0 * 8;
    const __nv_bfloat16* b0lp = g_Blo + (size_t)n0 * KDIM + h0 * 8;
    const __nv_bfloat16* b1hp = g_Bhi + (size_t)n1 * KDIM + h1 * 8;
    const __nv_bfloat16* b1lp = g_Blo + (size_t)n1 * KDIM + h1 * 8;

    float acc[25][4];
#pragma unroll
    for (int i = 0; i < 25; i++)
#pragma unroll
        for (int j = 0; j < 4; j++) acc[i][j] = 0.f;

    uint4 rAH, rB0H, rB0L, rB1H, rB1L;

    // ---- prologue: load k-step kbeg, store to buffer 0 ----
    {
        const int k16 = kbeg * 16;
        rAH  = *(const uint4*)(ahp + k16);
        rB0H = *(const uint4*)(b0hp + k16);
        rB0L = *(const uint4*)(b0lp + k16);
        if (has2) {
            rB1H = *(const uint4*)(b1hp + k16);
            rB1L = *(const uint4*)(b1lp + k16);
        }
        char* base = smem;
        *(uint4*)(base + SMA + a_row * 48 + a_half * 16) = rAH;
        *(uint4*)(base + SMB_HI + n0 * 48 + h0 * 16) = rB0H;
        *(uint4*)(base + SMB_LO + n0 * 48 + h0 * 16) = rB0L;
        if (has2) {
            *(uint4*)(base + SMB_HI + n1 * 48 + h1 * 16) = rB1H;
            *(uint4*)(base + SMB_LO + n1 * 48 + h1 * 16) = rB1L;
        }
    }

    int p = 0;
    for (int t = 0; t < iters; t++) {
        __syncthreads();
        const bool more = (t + 1 < iters);
        if (more) {
            const int k16 = (kbeg + t + 1) * 16;
            rAH  = *(const uint4*)(ahp + k16);
            rB0H = *(const uint4*)(b0hp + k16);
            rB0L = *(const uint4*)(b0lp + k16);
            if (has2) {
                rB1H = *(const uint4*)(b1hp + k16);
                rB1L = *(const uint4*)(b1lp + k16);
            }
        }

        // ---- compute on buffer p ----
        {
            const uint32_t bufb = sbase + (p ? SMBUF : 0);
            uint32_t ah[4];
            const uint32_t aaddr = bufb + SMA
                                 + (uint32_t)(warp * 16 + (lane & 15)) * 48
                                 + (uint32_t)(lane >> 4) * 16;
            ldsm4(ah, aaddr);

            const uint32_t baddr0 = bufb + SMB_HI
                                  + (uint32_t)(lane & 15) * 48
                                  + (uint32_t)(lane >> 4) * 16;
#pragma unroll
            for (int pr = 0; pr < 13; pr++) {
                uint32_t bh[4], bl[4];
                const uint32_t ba = baddr0 + (uint32_t)(pr * 16 * 48);
                ldsm4(bh, ba);
                ldsm4(bl, ba + (SMB_LO - SMB_HI));
                mma16816(acc[2*pr], ah, bh[0], bh[2]);
                mma16816(acc[2*pr], ah, bl[0], bl[2]);
                if (pr < 12) {
                    mma16816(acc[2*pr+1], ah, bh[1], bh[3]);
                    mma16816(acc[2*pr+1], ah, bl[1], bl[3]);
                }
            }
        }

        // ---- store next tile into buffer q ----
        if (more) {
            char* base = smem + (p ? 0 : SMBUF);
            *(uint4*)(base + SMA + a_row * 48 + a_half * 16) = rAH;
            *(uint4*)(base + SMB_HI + n0 * 48 + h0 * 16) = rB0H;
            *(uint4*)(base + SMB_LO + n0 * 48 + h0 * 16) = rB0L;
            if (has2) {
                *(uint4*)(base + SMB_HI + n1 * 48 + h1 * 16) = rB1H;
                *(uint4*)(base + SMB_LO + n1 * 48 + h1 * 16) = rB1L;
            }
        }
        p ^= 1;
    }

    // ---- epilogue: acc -> split-K partial ----
    float* cp = g_Cpart + (size_t)ks * CPART_STRIDE;
    const int rbase = m0 + warp * 16 + (lane >> 2);
    const int cbase = (lane & 3) * 2;
#pragma unroll
    for (int nt = 0; nt < 25; nt++) {
        const int n = nt * 8 + cbase;
        *(float2*)(cp + (size_t)rbase * DIM + n)       = make_float2(acc[nt][0], acc[nt][1]);
        *(float2*)(cp + (size_t)(rbase + 8) * DIM + n) = make_float2(acc[nt][2], acc[nt][3]);
    }
}

// ------------------------------ K5: zero out --------------------------------
__global__ void zero_kernel(float4* __restrict__ out) {
    const size_t total  = (size_t)EDGES * NNODES / 4;
    const size_t stride = (size_t)gridDim.x * blockDim.x;
    for (size_t i = (size_t)blockIdx.x * blockDim.x + threadIdx.x; i < total; i += stride)
        out[i] = make_float4(0.f, 0.f, 0.f, 0.f);
}

// ----------------- K6: split-K reduce (fixed order) + fc_b ------------------
__global__ void reduce_kernel(const float* __restrict__ fc_b) {
    const int i = blockIdx.x * 256 + threadIdx.x;
    const float4* p = (const float4*)g_Cpart;
    const size_t stride4 = CPART_STRIDE / 4;
    float4 s = p[i];
    float4 v = p[stride4 + i];
    s.x += v.x; s.y += v.y; s.z += v.z; s.w += v.w;
    const int n0 = (i * 4) % DIM;
    float4 bb = *(const float4*)(fc_b + n0);
    s.x += bb.x; s.y += bb.y; s.z += bb.z; s.w += bb.w;
    ((float4*)g_Y)[i] = s;
}

// --------------------------- K7: BN2 stats ----------------------------------
__global__ void bn2_kernel(const float* __restrict__ g2v, const float* __restrict__ be2v) {
    const int b   = blockIdx.x / DIM;
    const int n   = blockIdx.x - b * DIM;
    const int tid = threadIdx.x;

    __shared__ float ssum[256];
    __shared__ float ssq[256];

    float s = 0.f, q = 0.f;
    const float* base = g_Y + (size_t)(b * EDGES) * DIM + n;
#pragma unroll
    for (int u = 0; u < 8; u++) {
        float v = base[(size_t)(tid + u * 256) * DIM];
        s += v; q += v * v;
    }
    ssum[tid] = s; ssq[tid] = q;
    __syncthreads();
    for (int off = 128; off > 0; off >>= 1) {
        if (tid < off) { ssum[tid] += ssum[tid+off]; ssq[tid] += ssq[tid+off]; }
        __syncthreads();
    }
    if (tid == 0) {
        const float inv = 1.0f / (float)EDGES;
        float mu  = ssum[0] * inv;
        float var = ssq[0] * inv - mu * mu;
        float sc  = g2v[n] * rsqrtf(var + 1e-5f);
        g_bn2s[b * DIM + n] = sc;
        g_bn2h[b * DIM + n] = be2v[n] - mu * sc;
    }
}

// ----------------- K8: BN2+ReLU, cosine, scatter to output ------------------
__global__ void final_kernel(const int* __restrict__ o, float* __restrict__ out) {
    const int e    = blockIdx.x * 8 + (threadIdx.x >> 5);
    const int lane = threadIdx.x & 31;

    float dot[3] = {0.f,0.f,0.f}, nx[3] = {0.f,0.f,0.f}, nre = 0.f;
    for (int f = lane; f < DIM; f += 32) {
        float re = bn_relu(g_Y[(size_t)(3 * EDGES + e) * DIM + f],
                           g_bn2s[3 * DIM + f], g_bn2h[3 * DIM + f]);
        nre += re * re;
#pragma unroll
        for (int b = 0; b < 3; b++) {
            float xb = bn_relu(g_Y[(size_t)(b * EDGES + e) * DIM + f],
                               g_bn2s[b * DIM + f], g_bn2h[b * DIM + f]);
            dot[b] += xb * re;
            nx[b]  += xb * xb;
        }
    }
#pragma unroll
    for (int off = 16; off > 0; off >>= 1) {
        nre += __shfl_xor_sync(0xffffffffu, nre, off);
#pragma unroll
        for (int b = 0; b < 3; b++) {
            dot[b] += __shfl_xor_sync(0xffffffffu, dot[b], off);
            nx[b]  += __shfl_xor_sync(0xffffffffu, nx[b], off);
        }
    }
    if (lane == 0) {
        float nr = sqrtf(nre);
        float c = 0.f;
#pragma unroll
        for (int b = 0; b < 3; b++)
            c += dot[b] / fmaxf(sqrtf(nx[b]) * nr, 1e-8f);
        out[(size_t)e * NNODES + o[e]] = c;
    }
}

// ---------------------------------------------------------------------------
extern "C" void kernel_launch(void* const* d_in, const int* in_sizes, int n_in,
                              void* d_out, int out_size) {
    const float* pre_emb  = (const float*)d_in[0];
    const float* r_emb    = (const float*)d_in[1];
    const float* W2       = (const float*)d_in[2];
    const float* b2       = (const float*)d_in[3];
    const float* W3       = (const float*)d_in[4];
    const float* b3       = (const float*)d_in[5];
    const float* W4       = (const float*)d_in[6];
    const float* b4       = (const float*)d_in[7];
    const float* fc_w     = (const float*)d_in[8];
    const float* fc_b     = (const float*)d_in[9];
    const float* g1       = (const float*)d_in[10];
    const float* be1      = (const float*)d_in[11];
    const float* g2       = (const float*)d_in[12];
    const float* be2      = (const float*)d_in[13];
    const int*   src_ids  = (const int*)d_in[14];
    const int*   edge_type= (const int*)d_in[15];
    const int*   p1       = (const int*)d_in[16];
    const int*   p2       = (const int*)d_in[17];
    const int*   p3       = (const int*)d_in[18];
    const int*   o        = (const int*)d_in[19];
    float* out = (float*)d_out;

    cudaFuncSetAttribute(gemm_mma_kernel,
                         cudaFuncAttributeMaxDynamicSharedMemorySize, SMTOT);

    conv_kernel<<<dim3(EDGES, NBLK), 256>>>(pre_emb, r_emb, W2, b2, W3, b3, W4, b4,
                                            src_ids, edge_type, p1, p2, p3);
    statsr_kernel<<<NBLK * CH, 256>>>(g1, be1);
    splitAB_kernel<<<A_GROUPS + B_GROUPS, 256>>>(fc_w);
    gemm_mma_kernel<<<dim3(MROWS / 128, GSPLIT), 256, SMTOT>>>();
    zero_kernel<<<4096, 256>>>((float4*)out);
    reduce_kernel<<<(MROWS * DIM / 4) / 256, 256>>>(fc_b);
    bn2_kernel<<<NBLK * DIM, 256>>>(g2, be2);
    final_kernel<<<EDGES / 8, 256>>>(o, out);
}